// round 16
// baseline (speedup 1.0000x reference)
#include <cuda_runtime.h>
#include <cuda_fp16.h>
#include <cstdint>
#include <math.h>

// ---------------- problem constants ----------------
#define V_NODES 100000
#define F_DIM   512
#define D_DIM   512
#define C_DIM   128
#define N1_CNT  36864
#define S1_CNT  32768
#define B1_CNT  4096
#define S2_CNT  3584
#define B2_CNT  512

#define A_SCALE 32768.0f
#define A_INV   (1.0f / 32768.0f)

// ---------------- scratch (device globals) ----------------
__device__ float g_h1  [B1_CNT * D_DIM];
__device__ float g_h2  [B2_CNT * D_DIM];
__device__ __half  g_x16[(size_t)S1_CNT * F_DIM];    // X fp16 [32768,512] row-major
__device__ __half  g_a2 [(size_t)B2_CNT * S2_CNT];
__device__ __half  g_h1f16[(size_t)B1_CNT * D_DIM];
__device__ __half  g_c1 [(size_t)B1_CNT * 1024];
__device__ __half  g_c2 [(size_t)B2_CNT * 1024];
__device__ __half  g_w1h[1024 * D_DIM];
__device__ __half  g_w2h[1024 * D_DIM];

typedef unsigned long long u64t;

// ================= helpers =================
__device__ __forceinline__ uint32_t smem_u32(const void* p) {
    uint32_t a;
    asm("{ .reg .u64 t; cvta.to.shared.u64 t, %1; cvt.u32.u64 %0, t; }" : "=r"(a) : "l"(p));
    return a;
}
#define CP_ASYNC16(sm, gm) asm volatile("cp.async.cg.shared.global [%0], [%1], 16;" :: "r"(sm), "l"(gm) : "memory")
#define CP_COMMIT()        asm volatile("cp.async.commit_group;" ::: "memory")
#define CP_WAIT2()         asm volatile("cp.async.wait_group 2;" ::: "memory")
#define CP_WAIT4()         asm volatile("cp.async.wait_group 4;" ::: "memory")

__device__ __forceinline__ void ldsm_x4(uint32_t* r, uint32_t addr) {
    asm volatile("ldmatrix.sync.aligned.m8n8.x4.shared.b16 {%0,%1,%2,%3}, [%4];"
        : "=r"(r[0]), "=r"(r[1]), "=r"(r[2]), "=r"(r[3]) : "r"(addr));
}
__device__ __forceinline__ void ldsm_x4_t(uint32_t* r, uint32_t addr) {
    asm volatile("ldmatrix.sync.aligned.m8n8.x4.trans.shared.b16 {%0,%1,%2,%3}, [%4];"
        : "=r"(r[0]), "=r"(r[1]), "=r"(r[2]), "=r"(r[3]) : "r"(addr));
}
__device__ __forceinline__ void mma_f16(float* d, const uint32_t* a, const uint32_t* b) {
    asm volatile("mma.sync.aligned.m16n8k16.row.col.f32.f16.f16.f32 "
        "{%0,%1,%2,%3}, {%4,%5,%6,%7}, {%8,%9}, {%0,%1,%2,%3};"
        : "+f"(d[0]), "+f"(d[1]), "+f"(d[2]), "+f"(d[3])
        : "r"(a[0]), "r"(a[1]), "r"(a[2]), "r"(a[3]), "r"(b[0]), "r"(b[1]));
}
__device__ __forceinline__ uint32_t pack_h2(__half a, __half b) {
    __half2 t = __halves2half2(a, b);
    return *reinterpret_cast<uint32_t*>(&t);
}
__device__ __forceinline__ uint32_t cvt2_scaled(float x, float y) {
    return pack_h2(__float2half(x * A_SCALE), __float2half(y * A_SCALE));
}

// ================= small kernels =================
__global__ void gather_c1_kernel(const float* __restrict__ features,
                                 const int* __restrict__ dst_idx1,
                                 const int* __restrict__ src_nodes,
                                 __half* __restrict__ c1) {
    int b = blockIdx.x;
    int r = src_nodes[dst_idx1[b]];
    float4 v = reinterpret_cast<const float4*>(features + (size_t)r * 512)[threadIdx.x];
    reinterpret_cast<uint2*>(c1 + (size_t)b * 1024 + 512)[threadIdx.x] =
        make_uint2(pack_h2(__float2half(v.x), __float2half(v.y)),
                   pack_h2(__float2half(v.z), __float2half(v.w)));
}

__global__ void gather_c2_kernel(const __half* __restrict__ h1f16,
                                 const int* __restrict__ dst_idx2,
                                 __half* __restrict__ c2) {
    int b = blockIdx.x;
    int r = dst_idx2[b];
    reinterpret_cast<uint2*>(c2 + (size_t)b * 1024 + 512)[threadIdx.x] =
        reinterpret_cast<const uint2*>(h1f16 + (size_t)r * 512)[threadIdx.x];
}

// fp32 * 2^15 -> fp16 (8/thread) — layer-2 A only
__global__ void scale_f16_kernel(const float* __restrict__ src,
                                 __half* __restrict__ dst, int n8) {
    int i = blockIdx.x * blockDim.x + threadIdx.x;
    if (i >= n8) return;
    const float4* s = reinterpret_cast<const float4*>(src) + 2 * (size_t)i;
    float4 a = s[0], b = s[1];
    reinterpret_cast<uint4*>(dst)[i] = make_uint4(
        cvt2_scaled(a.x, a.y), cvt2_scaled(a.z, a.w),
        cvt2_scaled(b.x, b.y), cvt2_scaled(b.z, b.w));
}

// fp32 -> fp16 (4/thread)
__global__ void f32_to_f16_kernel(const float* __restrict__ src,
                                  __half* __restrict__ dst, int n4) {
    int i = blockIdx.x * blockDim.x + threadIdx.x;
    if (i >= n4) return;
    float4 v = reinterpret_cast<const float4*>(src)[i];
    reinterpret_cast<uint2*>(dst)[i] =
        make_uint2(pack_h2(__float2half(v.x), __float2half(v.y)),
                   pack_h2(__float2half(v.z), __float2half(v.w)));
}

// gather (composed index inline) + fp16, row-major
__global__ void prep_x_kernel(const float* __restrict__ features,
                              const int* __restrict__ src_idx1,
                              const int* __restrict__ src_nodes,
                              __half* __restrict__ x16) {
    const int k = blockIdx.x;
    const int r = src_nodes[src_idx1[k]];
    float4 v = reinterpret_cast<const float4*>(features + (size_t)r * F_DIM)[threadIdx.x];
    reinterpret_cast<uint2*>(x16 + (size_t)k * F_DIM)[threadIdx.x] =
        make_uint2(pack_h2(__float2half(v.x), __float2half(v.y)),
                   pack_h2(__float2half(v.z), __float2half(v.w)));
}

// ===== GEMM1: fp16 HMMA, A = fp32 dif_mat1 converted IN-KERNEL =====
// 512 thr, 16 warps (4m x 4n, 32x32), BK=64, 4 stages (A STS / B cp.async)
#define P_A_TILE 16384               // 128 rows x 128B (64 f16)
#define P_B_TILE 16384               // 64 krows x 256B (128 f16)
#define P_STAGE  (P_A_TILE + P_B_TILE)   // 32KB
#define P_NSTG   4
#define P_SMEM   (P_NSTG * P_STAGE)      // 128KB

__global__ __launch_bounds__(512, 1)
void gemm1_f16cvt(const float* __restrict__ A,
                  const __half* __restrict__ X,
                  __half* __restrict__ C) {
    constexpr int NCHUNK = S1_CNT / 64;   // 512
    constexpr int LDC = 1024;
    extern __shared__ __align__(128) char smem[];
    const uint32_t sb = smem_u32(smem);
    const int tid = threadIdx.x;
    const int wid = tid >> 5;
    const int lane = tid & 31;
    const int bm = blockIdx.y * 128;
    const int bn = blockIdx.x * 128;
    const int wm = (wid & 3) * 32;
    const int wn = (wid >> 2) * 32;

    float acc[2][4][4];
#pragma unroll
    for (int m = 0; m < 2; ++m)
#pragma unroll
        for (int n = 0; n < 4; ++n)
#pragma unroll
            for (int j = 0; j < 4; ++j) acc[m][n][j] = 0.f;

    // --- A (fp32 LDG -> cvt -> STS): thread t handles row t>>2, 16 floats at (t&3)*16 ---
    const int rA = tid >> 2, qA = tid & 3;
    const float* aP = A + (size_t)(bm + rA) * S1_CNT + qA * 16;
    const uint32_t sA0 = 2 * qA, sA1 = 2 * qA + 1;
    const uint32_t dA0 = rA * 128 + ((sA0 ^ (rA & 7)) << 4);
    const uint32_t dA1 = rA * 128 + ((sA1 ^ (rA & 7)) << 4);

    // --- B (cp.async, fp16): 2 lines of 16B per thread ---
    int rB0 = tid >> 4,          sB0 = tid & 15;
    int rB1 = (tid + 512) >> 4,  sB1 = (tid + 512) & 15;
    const __half* bP0 = X + (size_t)rB0 * F_DIM + bn + sB0 * 8;
    const __half* bP1 = X + (size_t)rB1 * F_DIM + bn + sB1 * 8;
    const uint32_t dB0 = P_A_TILE + rB0 * 256 + ((sB0 ^ (rB0 & 7)) << 4);
    const uint32_t dB1 = P_A_TILE + rB1 * 256 + ((sB1 ^ (rB1 & 7)) << 4);

    // hoisted ldsm offsets
    const uint32_t mrow0 = wm + (lane & 15);
    const uint32_t mrow1 = mrow0 + 16;
    const uint32_t acol  = (lane >> 4);
    uint32_t offA[2][4];
#pragma unroll
    for (int kk = 0; kk < 4; ++kk) {
        uint32_t cA = (uint32_t)(kk * 2) + acol;
        offA[0][kk] = mrow0 * 128 + ((cA ^ (mrow0 & 7)) << 4);
        offA[1][kk] = mrow1 * 128 + ((cA ^ (mrow1 & 7)) << 4);
    }
    const uint32_t krow = (lane & 15);
    uint32_t offB[2];
#pragma unroll
    for (int j = 0; j < 2; ++j) {
        uint32_t chk = (uint32_t)(wn >> 3) + j * 2 + (lane >> 4);
        offB[j] = P_A_TILE + krow * 256 + ((chk ^ (krow & 7)) << 4);
    }

    float4 aReg[4];
#define LDG_A(pred) do {                                                      \
    if (pred) {                                                               \
        aReg[0] = reinterpret_cast<const float4*>(aP)[0];                     \
        aReg[1] = reinterpret_cast<const float4*>(aP)[1];                     \
        aReg[2] = reinterpret_cast<const float4*>(aP)[2];                     \
        aReg[3] = reinterpret_cast<const float4*>(aP)[3];                     \
    }                                                                         \
    aP += 64;                                                                 \
} while (0)

#define STS_A(sbase) do {                                                     \
    uint4 h0 = make_uint4(cvt2_scaled(aReg[0].x, aReg[0].y),                  \
                          cvt2_scaled(aReg[0].z, aReg[0].w),                  \
                          cvt2_scaled(aReg[1].x, aReg[1].y),                  \
                          cvt2_scaled(aReg[1].z, aReg[1].w));                 \
    uint4 h1 = make_uint4(cvt2_scaled(aReg[2].x, aReg[2].y),                  \
                          cvt2_scaled(aReg[2].z, aReg[2].w),                  \
                          cvt2_scaled(aReg[3].x, aReg[3].y),                  \
                          cvt2_scaled(aReg[3].z, aReg[3].w));                 \
    asm volatile("st.shared.v4.b32 [%0], {%1,%2,%3,%4};" ::                   \
        "r"((sbase) + dA0), "r"(h0.x), "r"(h0.y), "r"(h0.z), "r"(h0.w));      \
    asm volatile("st.shared.v4.b32 [%0], {%1,%2,%3,%4};" ::                   \
        "r"((sbase) + dA1), "r"(h1.x), "r"(h1.y), "r"(h1.z), "r"(h1.w));      \
} while (0)

#define LOAD_B(pred, sbase) do {                                              \
    if (pred) {                                                               \
        CP_ASYNC16((sbase) + dB0, bP0);                                       \
        CP_ASYNC16((sbase) + dB1, bP1);                                       \
    }                                                                         \
    CP_COMMIT();                                                              \
    bP0 += (size_t)64 * F_DIM; bP1 += (size_t)64 * F_DIM;                     \
} while (0)

    // prologue: A(0) STS'd, A(1) in regs, B(0..2) committed
    LDG_A(true);
    STS_A(sb + 0 * P_STAGE);
    LDG_A(true);
    LOAD_B(true, sb + 0 * P_STAGE);
    LOAD_B(true, sb + 1 * P_STAGE);
    LOAD_B(true, sb + 2 * P_STAGE);

#pragma unroll 1
    for (int ch = 0; ch < NCHUNK; ++ch) {
        CP_WAIT2();            // B(ch) complete
        __syncthreads();       // A(ch) STS visible; stage (ch+3)&3 free
        LOAD_B(ch + 3 < NCHUNK, sb + (uint32_t)((ch + 3) & 3) * P_STAGE);
        if (ch + 1 < NCHUNK) STS_A(sb + (uint32_t)((ch + 1) & 3) * P_STAGE);
        LDG_A(ch + 2 < NCHUNK);

        const uint32_t abase = sb + (uint32_t)(ch & 3) * P_STAGE;
#pragma unroll
        for (int kk = 0; kk < 4; ++kk) {
            uint32_t ar[2][4], br[2][4];
            ldsm_x4(ar[0], abase + offA[0][kk]);
            ldsm_x4(ar[1], abase + offA[1][kk]);
            const uint32_t bstep = abase + (uint32_t)(kk * 4096);
            ldsm_x4_t(br[0], bstep + offB[0]);
            ldsm_x4_t(br[1], bstep + offB[1]);
#pragma unroll
            for (int m = 0; m < 2; ++m)
#pragma unroll
                for (int j = 0; j < 2; ++j)
#pragma unroll
                    for (int h = 0; h < 2; ++h)
                        mma_f16(acc[m][j * 2 + h], ar[m], &br[j][2 * h]);
        }
    }

    // epilogue: scale -> single fp16
#pragma unroll
    for (int m = 0; m < 2; ++m) {
#pragma unroll
        for (int half = 0; half < 2; ++half) {
            const int row = bm + wm + m * 16 + half * 8 + (lane >> 2);
#pragma unroll
            for (int n8 = 0; n8 < 4; ++n8) {
                const int col = bn + wn + n8 * 8 + (lane & 3) * 2;
                float v0 = acc[m][n8][2 * half + 0] * A_INV;
                float v1 = acc[m][n8][2 * half + 1] * A_INV;
                *reinterpret_cast<uint32_t*>(C + (size_t)row * LDC + col) =
                    pack_h2(__float2half(v0), __float2half(v1));
            }
        }
    }
#undef LDG_A
#undef STS_A
#undef LOAD_B
}

// ===== single-term fp16 GEMM: C = relu(A @ B) =====
#define T_A_TILE 16384
#define T_B_TILE 16384
#define T_STAGE  (T_A_TILE + T_B_TILE)
#define T_NSTG   4
#define T_SMEM   (T_NSTG * T_STAGE)

__global__ __launch_bounds__(256, 1)
void gemm_1t_f16(const __half* __restrict__ A,
                 const __half* __restrict__ B,
                 float* __restrict__ C,
                 __half* __restrict__ C16) {
    constexpr int NCHUNK = 16;
    constexpr int LDA = 1024, LDB = 512, LDC = 512;
    extern __shared__ __align__(128) char smem[];
    const uint32_t sb = smem_u32(smem);
    const int tid = threadIdx.x;
    const int wid = tid >> 5;
    const int lane = tid & 31;
    const int bm = blockIdx.y * 128;
    const int bn = blockIdx.x * 128;
    const int wm = (wid & 3) * 32;
    const int wn = (wid >> 2) * 64;

    float acc[2][8][4];
#pragma unroll
    for (int m = 0; m < 2; ++m)
#pragma unroll
        for (int n = 0; n < 8; ++n)
#pragma unroll
            for (int j = 0; j < 4; ++j) acc[m][n][j] = 0.f;

#define T_LOAD(ch) do {                                                       \
    if ((ch) < NCHUNK) {                                                      \
        size_t k0 = (size_t)(ch) * 64;                                        \
        uint32_t sa = sb + (uint32_t)((ch) % T_NSTG) * T_STAGE;               \
        uint32_t sB = sa + T_A_TILE;                                          \
        _Pragma("unroll")                                                     \
        for (int i = 0; i < 4; ++i) {                                         \
            int lin = tid + i * 256;                                          \
            int row = lin >> 3, seg = lin & 7;                                \
            uint32_t d = sa + row * 128 + (((seg ^ (row & 7))) << 4);         \
            CP_ASYNC16(d, A + (size_t)(bm + row) * LDA + k0 + seg * 8);       \
        }                                                                     \
        _Pragma("unroll")                                                     \
        for (int i = 0; i < 4; ++i) {                                         \
            int lin = tid + i * 256;                                          \
            int row = lin >> 4, chk = lin & 15;                               \
            uint32_t d = sB + row * 256 + (((chk ^ (row & 7))) << 4);         \
            CP_ASYNC16(d, B + (size_t)(k0 + row) * LDB + bn + chk * 8);       \
        }                                                                     \
    }                                                                         \
    CP_COMMIT();                                                              \
} while (0)

    T_LOAD(0); T_LOAD(1); T_LOAD(2);

    for (int ch = 0; ch < NCHUNK; ++ch) {
        CP_WAIT2();
        __syncthreads();
        T_LOAD(ch + 3);

        const uint32_t abase = sb + (uint32_t)(ch % T_NSTG) * T_STAGE;
        const uint32_t bbase = abase + T_A_TILE;
#pragma unroll
        for (int kk = 0; kk < 4; ++kk) {
            uint32_t ah[2][4];
#pragma unroll
            for (int m = 0; m < 2; ++m) {
                uint32_t r = wm + m * 16 + (lane & 15);
                uint32_t c = kk * 2 + (lane >> 4);
                ldsm_x4(ah[m], abase + r * 128 + ((c ^ (r & 7)) << 4));
            }
            uint32_t bh[4][4];
#pragma unroll
            for (int j = 0; j < 4; ++j) {
                uint32_t krow = kk * 16 + (lane & 15);
                uint32_t chk = (uint32_t)(wn >> 3) + j * 2 + (lane >> 4);
                ldsm_x4_t(bh[j], bbase + krow * 256 + ((chk ^ (krow & 7)) << 4));
            }
#pragma unroll
            for (int m = 0; m < 2; ++m)
#pragma unroll
                for (int j = 0; j < 4; ++j)
#pragma unroll
                    for (int h = 0; h < 2; ++h)
                        mma_f16(acc[m][j * 2 + h], ah[m], &bh[j][2 * h]);
        }
        __syncthreads();
    }

#pragma unroll
    for (int m = 0; m < 2; ++m) {
        const int row = bm + wm + m * 16 + (lane >> 2);
#pragma unroll
        for (int n8 = 0; n8 < 8; ++n8) {
            const int col = bn + wn + n8 * 8 + (lane & 3) * 2;
            float2 v0 = make_float2(fmaxf(acc[m][n8][0], 0.f), fmaxf(acc[m][n8][1], 0.f));
            float2 v1 = make_float2(fmaxf(acc[m][n8][2], 0.f), fmaxf(acc[m][n8][3], 0.f));
            *reinterpret_cast<float2*>(C + (size_t)row * LDC + col) = v0;
            *reinterpret_cast<float2*>(C + (size_t)(row + 8) * LDC + col) = v1;
            if (C16) {
                *reinterpret_cast<uint32_t*>(C16 + (size_t)row * LDC + col) =
                    pack_h2(__float2half(v0.x), __float2half(v0.y));
                *reinterpret_cast<uint32_t*>(C16 + (size_t)(row + 8) * LDC + col) =
                    pack_h2(__float2half(v1.x), __float2half(v1.y));
            }
        }
    }
#undef T_LOAD
}

// ===== GEMM2 (agg2): fp16 single, gathered B, fp16 epilogue =====
#define Q_A_TILE 16384
#define Q_B_TILE 16384
#define Q_STAGE  (Q_A_TILE + Q_B_TILE)
#define Q_NSTG   6
#define Q_SMEM   (Q_NSTG * Q_STAGE)

__global__ __launch_bounds__(256, 1)
void gemm2_f16(const __half* __restrict__ A,
               const __half* __restrict__ B,
               const int* __restrict__ gidx,
               __half* __restrict__ C) {
    constexpr int NCHUNK = S2_CNT / 64;
    constexpr int LDA = S2_CNT, LDB = D_DIM, LDC = 1024;
    extern __shared__ __align__(128) char smem[];
    const uint32_t sb = smem_u32(smem);
    const int tid = threadIdx.x;
    const int wid = tid >> 5;
    const int lane = tid & 31;
    const int bm = blockIdx.y * 128;
    const int bn = blockIdx.x * 128;
    const int wm = (wid & 3) * 32;
    const int wn = (wid >> 2) * 64;

    float acc[2][8][4];
#pragma unroll
    for (int m = 0; m < 2; ++m)
#pragma unroll
        for (int n = 0; n < 8; ++n)
#pragma unroll
            for (int j = 0; j < 4; ++j) acc[m][n][j] = 0.f;

#define Q_LOAD(ch) do {                                                       \
    if ((ch) < NCHUNK) {                                                      \
        size_t k0 = (size_t)(ch) * 64;                                        \
        uint32_t sa = sb + (uint32_t)((ch) % Q_NSTG) * Q_STAGE;               \
        uint32_t sB = sa + Q_A_TILE;                                          \
        _Pragma("unroll")                                                     \
        for (int i = 0; i < 4; ++i) {                                         \
            int lin = tid + i * 256;                                          \
            int row = lin >> 3, seg = lin & 7;                                \
            uint32_t d = sa + row * 128 + (((seg ^ (row & 7))) << 4);         \
            CP_ASYNC16(d, A + (size_t)(bm + row) * LDA + k0 + seg * 8);       \
        }                                                                     \
        _Pragma("unroll")                                                     \
        for (int i = 0; i < 4; ++i) {                                         \
            int lin = tid + i * 256;                                          \
            int row = lin >> 4, chk = lin & 15;                               \
            int g = gidx[k0 + row];                                           \
            uint32_t d = sB + row * 256 + (((chk ^ (row & 7))) << 4);         \
            CP_ASYNC16(d, B + (size_t)g * LDB + bn + chk * 8);                \
        }                                                                     \
    }                                                                         \
    CP_COMMIT();                                                              \
} while (0)

    Q_LOAD(0); Q_LOAD(1); Q_LOAD(2); Q_LOAD(3); Q_LOAD(4);

    for (int ch = 0; ch < NCHUNK; ++ch) {
        CP_WAIT4();
        __syncthreads();
        Q_LOAD(ch + 5);

        const uint32_t abase = sb + (uint32_t)(ch % Q_NSTG) * Q_STAGE;
        const uint32_t bbase = abase + Q_A_TILE;
#pragma unroll
        for (int kk = 0; kk < 4; ++kk) {
            uint32_t ah[2][4];
#pragma unroll
            for (int m = 0; m < 2; ++m) {
                uint32_t r = wm + m * 16 + (lane & 15);
                uint32_t c = kk * 2 + (lane >> 4);
                ldsm_x4(ah[m], abase + r * 128 + ((c ^ (r & 7)) << 4));
            }
            uint32_t bh[4][4];
#pragma unroll
            for (int j = 0; j < 4; ++j) {
                uint32_t krow = kk * 16 + (lane & 15);
                uint32_t chk = (uint32_t)(wn >> 3) + j * 2 + (lane >> 4);
                ldsm_x4_t(bh[j], bbase + krow * 256 + ((chk ^ (krow & 7)) << 4));
            }
#pragma unroll
            for (int m = 0; m < 2; ++m)
#pragma unroll
                for (int j = 0; j < 4; ++j)
#pragma unroll
                    for (int h = 0; h < 2; ++h)
                        mma_f16(acc[m][j * 2 + h], ah[m], &bh[j][2 * h]);
        }
        __syncthreads();
    }

#pragma unroll
    for (int m = 0; m < 2; ++m) {
        const int row = bm + wm + m * 16 + (lane >> 2);
#pragma unroll
        for (int n8 = 0; n8 < 8; ++n8) {
            const int col = bn + wn + n8 * 8 + (lane & 3) * 2;
            float v0 = acc[m][n8][0] * A_INV, v1 = acc[m][n8][1] * A_INV;
            float v2 = acc[m][n8][2] * A_INV, v3 = acc[m][n8][3] * A_INV;
            *reinterpret_cast<uint32_t*>(C + (size_t)row * LDC + col) =
                pack_h2(__float2half(v0), __float2half(v1));
            *reinterpret_cast<uint32_t*>(C + (size_t)(row + 8) * LDC + col) =
                pack_h2(__float2half(v2), __float2half(v3));
        }
    }
#undef Q_LOAD
}

// ================= classifier + softmax =================
__global__ void cls_softmax_kernel(const float* __restrict__ h2,
                                   const float* __restrict__ wc,
                                   float* __restrict__ out) {
    __shared__ float sh[D_DIM];
    __shared__ float red[C_DIM];
    const int b = blockIdx.x;
    const int c = threadIdx.x;
    for (int i = c; i < D_DIM; i += C_DIM) sh[i] = h2[(size_t)b * D_DIM + i];
    __syncthreads();
    float acc = 0.f;
#pragma unroll 8
    for (int k = 0; k < D_DIM; ++k)
        acc = fmaf(sh[k], wc[(size_t)k * C_DIM + c], acc);
    red[c] = acc;
    __syncthreads();
    for (int s = C_DIM / 2; s > 0; s >>= 1) {
        if (c < s) red[c] = fmaxf(red[c], red[c + s]);
        __syncthreads();
    }
    float mx = red[0];
    __syncthreads();
    float e = expf(acc - mx);
    red[c] = e;
    __syncthreads();
    for (int s = C_DIM / 2; s > 0; s >>= 1) {
        if (c < s) red[c] += red[c + s];
        __syncthreads();
    }
    out[(size_t)b * C_DIM + c] = e / red[0];
}

// ================= launch =================
extern "C" void kernel_launch(void* const* d_in, const int* in_sizes, int n_in,
                              void* d_out, int out_size) {
    const float* features  = (const float*)d_in[0];
    const int*   src_nodes = (const int*)d_in[1];
    const int*   dst_idx1  = (const int*)d_in[2];
    const int*   src_idx1  = (const int*)d_in[3];
    const float* dif_mat1  = (const float*)d_in[4];
    const int*   dst_idx2  = (const int*)d_in[5];
    const int*   src_idx2  = (const int*)d_in[6];
    const float* dif_mat2  = (const float*)d_in[7];
    const float* w1        = (const float*)d_in[8];
    const float* w2        = (const float*)d_in[9];
    const float* w_cls     = (const float*)d_in[10];
    float* out = (float*)d_out;

    float *h1, *h2;
    __half *x16, *a2, *h1f16, *c1, *c2, *w1h, *w2h;
    cudaGetSymbolAddress((void**)&h1,    g_h1);
    cudaGetSymbolAddress((void**)&h2,    g_h2);
    cudaGetSymbolAddress((void**)&x16,   g_x16);
    cudaGetSymbolAddress((void**)&a2,    g_a2);
    cudaGetSymbolAddress((void**)&h1f16, g_h1f16);
    cudaGetSymbolAddress((void**)&c1,    g_c1);
    cudaGetSymbolAddress((void**)&c2,    g_c2);
    cudaGetSymbolAddress((void**)&w1h,   g_w1h);
    cudaGetSymbolAddress((void**)&w2h,   g_w2h);

    cudaFuncSetAttribute((const void*)gemm1_f16cvt,
                         cudaFuncAttributeMaxDynamicSharedMemorySize, P_SMEM);
    cudaFuncSetAttribute((const void*)gemm_1t_f16,
                         cudaFuncAttributeMaxDynamicSharedMemorySize, T_SMEM);
    cudaFuncSetAttribute((const void*)gemm2_f16,
                         cudaFuncAttributeMaxDynamicSharedMemorySize, Q_SMEM);

    // launches 1-3: prep (gemm1 lands 4th for the ncu snapshot)
    f32_to_f16_kernel<<<(1024 * D_DIM / 4) / 256, 256>>>(w1, w1h, 1024 * D_DIM / 4);
    prep_x_kernel<<<S1_CNT, 128>>>(features, src_idx1, src_nodes, x16);
    gather_c1_kernel<<<B1_CNT, 128>>>(features, dst_idx1, src_nodes, c1);

    // 4: agg1 -> c1[:, 0:512] fp16 (fp16 HMMA, A converted in-kernel)
    gemm1_f16cvt<<<dim3(F_DIM / 128, B1_CNT / 128), 512, P_SMEM>>>(dif_mat1, x16, c1);

    f32_to_f16_kernel<<<(1024 * D_DIM / 4) / 256, 256>>>(w2, w2h, 1024 * D_DIM / 4);

    // h1 = relu(c1 @ w1), co-emit fp16
    gemm_1t_f16<<<dim3(D_DIM / 128, B1_CNT / 128), 256, T_SMEM>>>(c1, w1h, h1, h1f16);

    // layer 2
    {
        int a8n = (B2_CNT * S2_CNT) / 8;
        scale_f16_kernel<<<(a8n + 255) / 256, 256>>>(dif_mat2, a2, a8n);
    }
    gather_c2_kernel<<<B2_CNT, 128>>>(h1f16, dst_idx2, c2);
    gemm2_f16<<<dim3(D_DIM / 128, B2_CNT / 128), 256, Q_SMEM>>>(a2, h1f16, src_idx2, c2);
    gemm_1t_f16<<<dim3(D_DIM / 128, B2_CNT / 128), 256, T_SMEM>>>(c2, w2h, h2, (__half*)nullptr);

    cls_softmax_kernel<<<B2_CNT, C_DIM>>>(h2, w_cls, out);
}

// round 17
// speedup vs baseline: 1.3606x; 1.3606x over previous
#include <cuda_runtime.h>
#include <cuda_fp16.h>
#include <cstdint>
#include <math.h>

// ---------------- problem constants ----------------
#define V_NODES 100000
#define F_DIM   512
#define D_DIM   512
#define C_DIM   128
#define N1_CNT  36864
#define S1_CNT  32768
#define B1_CNT  4096
#define S2_CNT  3584
#define B2_CNT  512

#define A_SCALE 32768.0f
#define A_INV   (1.0f / 32768.0f)

// ---------------- scratch (device globals) ----------------
__device__ float g_h1  [B1_CNT * D_DIM];
__device__ float g_h2  [B2_CNT * D_DIM];
__device__ uint8_t g_a8 [(size_t)B1_CNT * S1_CNT];
__device__ uint8_t g_xt8[(size_t)F_DIM * S1_CNT];
__device__ __half  g_a2 [(size_t)B2_CNT * S2_CNT];
__device__ __half  g_h1f16[(size_t)B1_CNT * D_DIM];
__device__ __half  g_c1 [(size_t)B1_CNT * 1024];
__device__ __half  g_c2 [(size_t)B2_CNT * 1024];
__device__ __half  g_w1h[1024 * D_DIM];
__device__ __half  g_w2h[1024 * D_DIM];

typedef unsigned long long u64t;

// ================= helpers =================
__device__ __forceinline__ uint32_t smem_u32(const void* p) {
    uint32_t a;
    asm("{ .reg .u64 t; cvta.to.shared.u64 t, %1; cvt.u32.u64 %0, t; }" : "=r"(a) : "l"(p));
    return a;
}
#define CP_ASYNC16(sm, gm) asm volatile("cp.async.cg.shared.global [%0], [%1], 16;" :: "r"(sm), "l"(gm) : "memory")
#define CP_COMMIT()        asm volatile("cp.async.commit_group;" ::: "memory")
#define CP_WAIT2()         asm volatile("cp.async.wait_group 2;" ::: "memory")
#define CP_WAIT3()         asm volatile("cp.async.wait_group 3;" ::: "memory")
#define CP_WAIT4()         asm volatile("cp.async.wait_group 4;" ::: "memory")

__device__ __forceinline__ void ldsm_x4(uint32_t* r, uint32_t addr) {
    asm volatile("ldmatrix.sync.aligned.m8n8.x4.shared.b16 {%0,%1,%2,%3}, [%4];"
        : "=r"(r[0]), "=r"(r[1]), "=r"(r[2]), "=r"(r[3]) : "r"(addr));
}
__device__ __forceinline__ void ldsm_x4_t(uint32_t* r, uint32_t addr) {
    asm volatile("ldmatrix.sync.aligned.m8n8.x4.trans.shared.b16 {%0,%1,%2,%3}, [%4];"
        : "=r"(r[0]), "=r"(r[1]), "=r"(r[2]), "=r"(r[3]) : "r"(addr));
}
__device__ __forceinline__ void mma_f16(float* d, const uint32_t* a, const uint32_t* b) {
    asm volatile("mma.sync.aligned.m16n8k16.row.col.f32.f16.f16.f32 "
        "{%0,%1,%2,%3}, {%4,%5,%6,%7}, {%8,%9}, {%0,%1,%2,%3};"
        : "+f"(d[0]), "+f"(d[1]), "+f"(d[2]), "+f"(d[3])
        : "r"(a[0]), "r"(a[1]), "r"(a[2]), "r"(a[3]), "r"(b[0]), "r"(b[1]));
}
__device__ __forceinline__ void mma_fp8(float* d, const uint32_t* a, const uint32_t* b) {
    asm volatile("mma.sync.aligned.m16n8k32.row.col.f32.e4m3.e4m3.f32 "
        "{%0,%1,%2,%3}, {%4,%5,%6,%7}, {%8,%9}, {%0,%1,%2,%3};"
        : "+f"(d[0]), "+f"(d[1]), "+f"(d[2]), "+f"(d[3])
        : "r"(a[0]), "r"(a[1]), "r"(a[2]), "r"(a[3]), "r"(b[0]), "r"(b[1]));
}
__device__ __forceinline__ uint32_t pack_h2(__half a, __half b) {
    __half2 t = __halves2half2(a, b);
    return *reinterpret_cast<uint32_t*>(&t);
}
__device__ __forceinline__ uint32_t pack_e4m3_4(float f0, float f1, float f2, float f3) {
    uint16_t lo, hi;
    asm("cvt.rn.satfinite.e4m3x2.f32 %0, %1, %2;" : "=h"(lo) : "f"(f1), "f"(f0));
    asm("cvt.rn.satfinite.e4m3x2.f32 %0, %1, %2;" : "=h"(hi) : "f"(f3), "f"(f2));
    return (uint32_t)lo | ((uint32_t)hi << 16);
}

// ================= small kernels =================
__global__ void gather_c1_kernel(const float* __restrict__ features,
                                 const int* __restrict__ dst_idx1,
                                 const int* __restrict__ src_nodes,
                                 __half* __restrict__ c1) {
    int b = blockIdx.x;
    int r = src_nodes[dst_idx1[b]];
    float4 v = reinterpret_cast<const float4*>(features + (size_t)r * 512)[threadIdx.x];
    reinterpret_cast<uint2*>(c1 + (size_t)b * 1024 + 512)[threadIdx.x] =
        make_uint2(pack_h2(__float2half(v.x), __float2half(v.y)),
                   pack_h2(__float2half(v.z), __float2half(v.w)));
}

__global__ void gather_c2_kernel(const __half* __restrict__ h1f16,
                                 const int* __restrict__ dst_idx2,
                                 __half* __restrict__ c2) {
    int b = blockIdx.x;
    int r = dst_idx2[b];
    reinterpret_cast<uint2*>(c2 + (size_t)b * 1024 + 512)[threadIdx.x] =
        reinterpret_cast<const uint2*>(h1f16 + (size_t)r * 512)[threadIdx.x];
}

// fp32 * 2^15 -> e4m3 (8/thread)
__global__ void scale_a8_kernel(const float* __restrict__ src,
                                uint8_t* __restrict__ dst, int n8) {
    int i = blockIdx.x * blockDim.x + threadIdx.x;
    if (i >= n8) return;
    const float4* s = reinterpret_cast<const float4*>(src) + 2 * (size_t)i;
    float4 a = s[0], b = s[1];
    uint32_t p0 = pack_e4m3_4(a.x * A_SCALE, a.y * A_SCALE, a.z * A_SCALE, a.w * A_SCALE);
    uint32_t p1 = pack_e4m3_4(b.x * A_SCALE, b.y * A_SCALE, b.z * A_SCALE, b.w * A_SCALE);
    reinterpret_cast<uint2*>(dst)[i] = make_uint2(p0, p1);
}

// fp32 * 2^15 -> fp16 (8/thread)
__global__ void scale_f16_kernel(const float* __restrict__ src,
                                 __half* __restrict__ dst, int n8) {
    int i = blockIdx.x * blockDim.x + threadIdx.x;
    if (i >= n8) return;
    const float4* s = reinterpret_cast<const float4*>(src) + 2 * (size_t)i;
    float4 a = s[0], b = s[1];
    float f[8] = {a.x, a.y, a.z, a.w, b.x, b.y, b.z, b.w};
    __half h[8];
#pragma unroll
    for (int q = 0; q < 8; ++q) h[q] = __float2half(f[q] * A_SCALE);
    reinterpret_cast<uint4*>(dst)[i] = make_uint4(
        pack_h2(h[0], h[1]), pack_h2(h[2], h[3]),
        pack_h2(h[4], h[5]), pack_h2(h[6], h[7]));
}

// fp32 -> fp16 (4/thread)
__global__ void f32_to_f16_kernel(const float* __restrict__ src,
                                  __half* __restrict__ dst, int n4) {
    int i = blockIdx.x * blockDim.x + threadIdx.x;
    if (i >= n4) return;
    float4 v = reinterpret_cast<const float4*>(src)[i];
    reinterpret_cast<uint2*>(dst)[i] =
        make_uint2(pack_h2(__float2half(v.x), __float2half(v.y)),
                   pack_h2(__float2half(v.z), __float2half(v.w)));
}

// gather (composed index inline) + transpose + e4m3
__global__ void prep_xt8_kernel(const float* __restrict__ features,
                                const int* __restrict__ src_idx1,
                                const int* __restrict__ src_nodes,
                                uint8_t* __restrict__ xt) {
    __shared__ float tile[128][65];
    const int k0 = blockIdx.x * 128;
    const int n0 = blockIdx.y * 64;
    const int tid = threadIdx.x;
    for (int i = tid; i < 128 * 16; i += 128) {
        int r = i >> 4, c4 = i & 15;
        int row = src_nodes[src_idx1[k0 + r]];
        float4 v = *reinterpret_cast<const float4*>(
            features + (size_t)row * F_DIM + n0 + c4 * 4);
        tile[r][c4 * 4 + 0] = v.x; tile[r][c4 * 4 + 1] = v.y;
        tile[r][c4 * 4 + 2] = v.z; tile[r][c4 * 4 + 3] = v.w;
    }
    __syncthreads();
    for (int i = tid; i < 64 * 32; i += 128) {
        int n = i >> 5, kg = i & 31;
        uint32_t p = pack_e4m3_4(tile[kg * 4 + 0][n], tile[kg * 4 + 1][n],
                                 tile[kg * 4 + 2][n], tile[kg * 4 + 3][n]);
        *reinterpret_cast<uint32_t*>(xt + (size_t)(n0 + n) * S1_CNT + k0 + kg * 4) = p;
    }
}

// ===== GEMM1: fp8 (R11/R14 config), 512 thr, 5-stage, fp16 epilogue =====
#define P_A_TILE 16384
#define P_B_TILE 16384
#define P_STAGE  (P_A_TILE + P_B_TILE)   // 32KB
#define P_NSTG   5
#define P_SMEM   (P_NSTG * P_STAGE)      // 160KB

__global__ __launch_bounds__(512, 1)
void gemm1_fp8(const uint8_t* __restrict__ A,
               const uint8_t* __restrict__ Bt,
               __half* __restrict__ C) {
    constexpr int NCHUNK = S1_CNT / 128;   // 256
    constexpr int LDC = 1024;
    extern __shared__ __align__(128) char smem[];
    const uint32_t sb = smem_u32(smem);
    const int tid = threadIdx.x;
    const int wid = tid >> 5;
    const int lane = tid & 31;
    const int bm = blockIdx.y * 128;
    const int bn = blockIdx.x * 128;
    const int wm = (wid & 3) * 32;
    const int wn = (wid >> 2) * 32;

    float acc[2][4][4];
#pragma unroll
    for (int m = 0; m < 2; ++m)
#pragma unroll
        for (int n = 0; n < 4; ++n)
#pragma unroll
            for (int j = 0; j < 4; ++j) acc[m][n][j] = 0.f;

    int rA0 = tid >> 3,          sA0 = tid & 7;
    int rA1 = (tid + 512) >> 3,  sA1 = (tid + 512) & 7;
    const uint8_t* aP0 = A + (size_t)(bm + rA0) * S1_CNT + sA0 * 16;
    const uint8_t* aP1 = A + (size_t)(bm + rA1) * S1_CNT + sA1 * 16;
    const uint8_t* bP0 = Bt + (size_t)(bn + rA0) * S1_CNT + sA0 * 16;
    const uint8_t* bP1 = Bt + (size_t)(bn + rA1) * S1_CNT + sA1 * 16;
    const uint32_t dA0 = rA0 * 128 + ((sA0 ^ (rA0 & 7)) << 4);
    const uint32_t dA1 = rA1 * 128 + ((sA1 ^ (rA1 & 7)) << 4);

    const uint32_t mrow0 = wm + (lane & 15);
    const uint32_t mrow1 = mrow0 + 16;
    const uint32_t acol  = (lane >> 4);
    const uint32_t nrow0 = wn + (lane & 7) + ((lane & 16) >> 1);
    const uint32_t nrow1 = nrow0 + 16;
    const uint32_t bcol  = (lane >> 3) & 1;
    uint32_t offA[2][4], offB[2][4];
#pragma unroll
    for (int kk = 0; kk < 4; ++kk) {
        uint32_t cA = (uint32_t)(kk * 2) + acol;
        uint32_t cB = (uint32_t)(kk * 2) + bcol;
        offA[0][kk] = mrow0 * 128 + ((cA ^ (mrow0 & 7)) << 4);
        offA[1][kk] = mrow1 * 128 + ((cA ^ (mrow1 & 7)) << 4);
        offB[0][kk] = P_A_TILE + nrow0 * 128 + ((cB ^ (nrow0 & 7)) << 4);
        offB[1][kk] = P_A_TILE + nrow1 * 128 + ((cB ^ (nrow1 & 7)) << 4);
    }

#define P_LOAD(pred, sbase) do {                                              \
    if (pred) {                                                               \
        CP_ASYNC16((sbase) + dA0, aP0);                                       \
        CP_ASYNC16((sbase) + dA1, aP1);                                       \
        CP_ASYNC16((sbase) + P_A_TILE + dA0, bP0);                            \
        CP_ASYNC16((sbase) + P_A_TILE + dA1, bP1);                            \
    }                                                                         \
    CP_COMMIT();                                                              \
    aP0 += 128; aP1 += 128; bP0 += 128; bP1 += 128;                           \
} while (0)

    P_LOAD(true, sb + 0 * P_STAGE);
    P_LOAD(true, sb + 1 * P_STAGE);
    P_LOAD(true, sb + 2 * P_STAGE);
    P_LOAD(true, sb + 3 * P_STAGE);

    uint32_t cmp_base = sb;
    uint32_t load_base = sb + 4 * P_STAGE;
    const uint32_t smem_end = sb + P_NSTG * P_STAGE;

#pragma unroll 1
    for (int ch = 0; ch < NCHUNK; ++ch) {
        CP_WAIT3();
        __syncthreads();
        P_LOAD(ch + 4 < NCHUNK, load_base);
        load_base += P_STAGE; if (load_base == smem_end) load_base = sb;

        const uint32_t abase = cmp_base;
#pragma unroll
        for (int kk = 0; kk < 4; ++kk) {
            uint32_t ar[2][4], br[2][4];
            ldsm_x4(ar[0], abase + offA[0][kk]);
            ldsm_x4(ar[1], abase + offA[1][kk]);
            ldsm_x4(br[0], abase + offB[0][kk]);
            ldsm_x4(br[1], abase + offB[1][kk]);
#pragma unroll
            for (int m = 0; m < 2; ++m)
#pragma unroll
                for (int j = 0; j < 2; ++j)
#pragma unroll
                    for (int h = 0; h < 2; ++h)
                        mma_fp8(acc[m][j * 2 + h], ar[m], &br[j][2 * h]);
        }
        cmp_base += P_STAGE; if (cmp_base == smem_end) cmp_base = sb;
    }

#pragma unroll
    for (int m = 0; m < 2; ++m) {
#pragma unroll
        for (int half = 0; half < 2; ++half) {
            const int row = bm + wm + m * 16 + half * 8 + (lane >> 2);
#pragma unroll
            for (int n8 = 0; n8 < 4; ++n8) {
                const int col = bn + wn + n8 * 8 + (lane & 3) * 2;
                float v0 = acc[m][n8][2 * half + 0] * A_INV;
                float v1 = acc[m][n8][2 * half + 1] * A_INV;
                *reinterpret_cast<uint32_t*>(C + (size_t)row * LDC + col) =
                    pack_h2(__float2half(v0), __float2half(v1));
            }
        }
    }
#undef P_LOAD
}

// ===== single-term fp16 GEMM: C = relu(A @ B) =====
#define T_A_TILE 16384
#define T_B_TILE 16384
#define T_STAGE  (T_A_TILE + T_B_TILE)
#define T_NSTG   4
#define T_SMEM   (T_NSTG * T_STAGE)

__global__ __launch_bounds__(256, 1)
void gemm_1t_f16(const __half* __restrict__ A,
                 const __half* __restrict__ B,
                 float* __restrict__ C,
                 __half* __restrict__ C16) {
    constexpr int NCHUNK = 16;
    constexpr int LDA = 1024, LDB = 512, LDC = 512;
    extern __shared__ __align__(128) char smem[];
    const uint32_t sb = smem_u32(smem);
    const int tid = threadIdx.x;
    const int wid = tid >> 5;
    const int lane = tid & 31;
    const int bm = blockIdx.y * 128;
    const int bn = blockIdx.x * 128;
    const int wm = (wid & 3) * 32;
    const int wn = (wid >> 2) * 64;

    float acc[2][8][4];
#pragma unroll
    for (int m = 0; m < 2; ++m)
#pragma unroll
        for (int n = 0; n < 8; ++n)
#pragma unroll
            for (int j = 0; j < 4; ++j) acc[m][n][j] = 0.f;

#define T_LOAD(ch) do {                                                       \
    if ((ch) < NCHUNK) {                                                      \
        size_t k0 = (size_t)(ch) * 64;                                        \
        uint32_t sa = sb + (uint32_t)((ch) % T_NSTG) * T_STAGE;               \
        uint32_t sB = sa + T_A_TILE;                                          \
        _Pragma("unroll")                                                     \
        for (int i = 0; i < 4; ++i) {                                         \
            int lin = tid + i * 256;                                          \
            int row = lin >> 3, seg = lin & 7;                                \
            uint32_t d = sa + row * 128 + (((seg ^ (row & 7))) << 4);         \
            CP_ASYNC16(d, A + (size_t)(bm + row) * LDA + k0 + seg * 8);       \
        }                                                                     \
        _Pragma("unroll")                                                     \
        for (int i = 0; i < 4; ++i) {                                         \
            int lin = tid + i * 256;                                          \
            int row = lin >> 4, chk = lin & 15;                               \
            uint32_t d = sB + row * 256 + (((chk ^ (row & 7))) << 4);         \
            CP_ASYNC16(d, B + (size_t)(k0 + row) * LDB + bn + chk * 8);       \
        }                                                                     \
    }                                                                         \
    CP_COMMIT();                                                              \
} while (0)

    T_LOAD(0); T_LOAD(1); T_LOAD(2);

    for (int ch = 0; ch < NCHUNK; ++ch) {
        CP_WAIT2();
        __syncthreads();
        T_LOAD(ch + 3);

        const uint32_t abase = sb + (uint32_t)(ch % T_NSTG) * T_STAGE;
        const uint32_t bbase = abase + T_A_TILE;
#pragma unroll
        for (int kk = 0; kk < 4; ++kk) {
            uint32_t ah[2][4];
#pragma unroll
            for (int m = 0; m < 2; ++m) {
                uint32_t r = wm + m * 16 + (lane & 15);
                uint32_t c = kk * 2 + (lane >> 4);
                ldsm_x4(ah[m], abase + r * 128 + ((c ^ (r & 7)) << 4));
            }
            uint32_t bh[4][4];
#pragma unroll
            for (int j = 0; j < 4; ++j) {
                uint32_t krow = kk * 16 + (lane & 15);
                uint32_t chk = (uint32_t)(wn >> 3) + j * 2 + (lane >> 4);
                ldsm_x4_t(bh[j], bbase + krow * 256 + ((chk ^ (krow & 7)) << 4));
            }
#pragma unroll
            for (int m = 0; m < 2; ++m)
#pragma unroll
                for (int j = 0; j < 4; ++j)
#pragma unroll
                    for (int h = 0; h < 2; ++h)
                        mma_f16(acc[m][j * 2 + h], ah[m], &bh[j][2 * h]);
        }
        __syncthreads();
    }

#pragma unroll
    for (int m = 0; m < 2; ++m) {
        const int row = bm + wm + m * 16 + (lane >> 2);
#pragma unroll
        for (int n8 = 0; n8 < 8; ++n8) {
            const int col = bn + wn + n8 * 8 + (lane & 3) * 2;
            float2 v0 = make_float2(fmaxf(acc[m][n8][0], 0.f), fmaxf(acc[m][n8][1], 0.f));
            float2 v1 = make_float2(fmaxf(acc[m][n8][2], 0.f), fmaxf(acc[m][n8][3], 0.f));
            *reinterpret_cast<float2*>(C + (size_t)row * LDC + col) = v0;
            *reinterpret_cast<float2*>(C + (size_t)(row + 8) * LDC + col) = v1;
            if (C16) {
                *reinterpret_cast<uint32_t*>(C16 + (size_t)row * LDC + col) =
                    pack_h2(__float2half(v0.x), __float2half(v0.y));
                *reinterpret_cast<uint32_t*>(C16 + (size_t)(row + 8) * LDC + col) =
                    pack_h2(__float2half(v1.x), __float2half(v1.y));
            }
        }
    }
#undef T_LOAD
}

// ===== GEMM2 (agg2): fp16 single, gathered B, fp16 epilogue =====
#define Q_A_TILE 16384
#define Q_B_TILE 16384
#define Q_STAGE  (Q_A_TILE + Q_B_TILE)
#define Q_NSTG   6
#define Q_SMEM   (Q_NSTG * Q_STAGE)

__global__ __launch_bounds__(256, 1)
void gemm2_f16(const __half* __restrict__ A,
               const __half* __restrict__ B,
               const int* __restrict__ gidx,
               __half* __restrict__ C) {
    constexpr int NCHUNK = S2_CNT / 64;
    constexpr int LDA = S2_CNT, LDB = D_DIM, LDC = 1024;
    extern __shared__ __align__(128) char smem[];
    const uint32_t sb = smem_u32(smem);
    const int tid = threadIdx.x;
    const int wid = tid >> 5;
    const int lane = tid & 31;
    const int bm = blockIdx.y * 128;
    const int bn = blockIdx.x * 128;
    const int wm = (wid & 3) * 32;
    const int wn = (wid >> 2) * 64;

    float acc[2][8][4];
#pragma unroll
    for (int m = 0; m < 2; ++m)
#pragma unroll
        for (int n = 0; n < 8; ++n)
#pragma unroll
            for (int j = 0; j < 4; ++j) acc[m][n][j] = 0.f;

#define Q_LOAD(ch) do {                                                       \
    if ((ch) < NCHUNK) {                                                      \
        size_t k0 = (size_t)(ch) * 64;                                        \
        uint32_t sa = sb + (uint32_t)((ch) % Q_NSTG) * Q_STAGE;               \
        uint32_t sB = sa + Q_A_TILE;                                          \
        _Pragma("unroll")                                                     \
        for (int i = 0; i < 4; ++i) {                                         \
            int lin = tid + i * 256;                                          \
            int row = lin >> 3, seg = lin & 7;                                \
            uint32_t d = sa + row * 128 + (((seg ^ (row & 7))) << 4);         \
            CP_ASYNC16(d, A + (size_t)(bm + row) * LDA + k0 + seg * 8);       \
        }                                                                     \
        _Pragma("unroll")                                                     \
        for (int i = 0; i < 4; ++i) {                                         \
            int lin = tid + i * 256;                                          \
            int row = lin >> 4, chk = lin & 15;                               \
            int g = gidx[k0 + row];                                           \
            uint32_t d = sB + row * 256 + (((chk ^ (row & 7))) << 4);         \
            CP_ASYNC16(d, B + (size_t)g * LDB + bn + chk * 8);                \
        }                                                                     \
    }                                                                         \
    CP_COMMIT();                                                              \
} while (0)

    Q_LOAD(0); Q_LOAD(1); Q_LOAD(2); Q_LOAD(3); Q_LOAD(4);

    for (int ch = 0; ch < NCHUNK; ++ch) {
        CP_WAIT4();
        __syncthreads();
        Q_LOAD(ch + 5);

        const uint32_t abase = sb + (uint32_t)(ch % Q_NSTG) * Q_STAGE;
        const uint32_t bbase = abase + Q_A_TILE;
#pragma unroll
        for (int kk = 0; kk < 4; ++kk) {
            uint32_t ah[2][4];
#pragma unroll
            for (int m = 0; m < 2; ++m) {
                uint32_t r = wm + m * 16 + (lane & 15);
                uint32_t c = kk * 2 + (lane >> 4);
                ldsm_x4(ah[m], abase + r * 128 + ((c ^ (r & 7)) << 4));
            }
            uint32_t bh[4][4];
#pragma unroll
            for (int j = 0; j < 4; ++j) {
                uint32_t krow = kk * 16 + (lane & 15);
                uint32_t chk = (uint32_t)(wn >> 3) + j * 2 + (lane >> 4);
                ldsm_x4_t(bh[j], bbase + krow * 256 + ((chk ^ (krow & 7)) << 4));
            }
#pragma unroll
            for (int m = 0; m < 2; ++m)
#pragma unroll
                for (int j = 0; j < 4; ++j)
#pragma unroll
                    for (int h = 0; h < 2; ++h)
                        mma_f16(acc[m][j * 2 + h], ah[m], &bh[j][2 * h]);
        }
        __syncthreads();
    }

#pragma unroll
    for (int m = 0; m < 2; ++m) {
        const int row = bm + wm + m * 16 + (lane >> 2);
#pragma unroll
        for (int n8 = 0; n8 < 8; ++n8) {
            const int col = bn + wn + n8 * 8 + (lane & 3) * 2;
            float v0 = acc[m][n8][0] * A_INV, v1 = acc[m][n8][1] * A_INV;
            float v2 = acc[m][n8][2] * A_INV, v3 = acc[m][n8][3] * A_INV;
            *reinterpret_cast<uint32_t*>(C + (size_t)row * LDC + col) =
                pack_h2(__float2half(v0), __float2half(v1));
            *reinterpret_cast<uint32_t*>(C + (size_t)(row + 8) * LDC + col) =
                pack_h2(__float2half(v2), __float2half(v3));
        }
    }
#undef Q_LOAD
}

// ================= classifier + softmax =================
__global__ void cls_softmax_kernel(const float* __restrict__ h2,
                                   const float* __restrict__ wc,
                                   float* __restrict__ out) {
    __shared__ float sh[D_DIM];
    __shared__ float red[C_DIM];
    const int b = blockIdx.x;
    const int c = threadIdx.x;
    for (int i = c; i < D_DIM; i += C_DIM) sh[i] = h2[(size_t)b * D_DIM + i];
    __syncthreads();
    float acc = 0.f;
#pragma unroll 8
    for (int k = 0; k < D_DIM; ++k)
        acc = fmaf(sh[k], wc[(size_t)k * C_DIM + c], acc);
    red[c] = acc;
    __syncthreads();
    for (int s = C_DIM / 2; s > 0; s >>= 1) {
        if (c < s) red[c] = fmaxf(red[c], red[c + s]);
        __syncthreads();
    }
    float mx = red[0];
    __syncthreads();
    float e = expf(acc - mx);
    red[c] = e;
    __syncthreads();
    for (int s = C_DIM / 2; s > 0; s >>= 1) {
        if (c < s) red[c] += red[c + s];
        __syncthreads();
    }
    out[(size_t)b * C_DIM + c] = e / red[0];
}

// ================= launch =================
extern "C" void kernel_launch(void* const* d_in, const int* in_sizes, int n_in,
                              void* d_out, int out_size) {
    const float* features  = (const float*)d_in[0];
    const int*   src_nodes = (const int*)d_in[1];
    const int*   dst_idx1  = (const int*)d_in[2];
    const int*   src_idx1  = (const int*)d_in[3];
    const float* dif_mat1  = (const float*)d_in[4];
    const int*   dst_idx2  = (const int*)d_in[5];
    const int*   src_idx2  = (const int*)d_in[6];
    const float* dif_mat2  = (const float*)d_in[7];
    const float* w1        = (const float*)d_in[8];
    const float* w2        = (const float*)d_in[9];
    const float* w_cls     = (const float*)d_in[10];
    float* out = (float*)d_out;

    float *h1, *h2;
    uint8_t *a8, *xt8;
    __half *a2, *h1f16, *c1, *c2, *w1h, *w2h;
    cudaGetSymbolAddress((void**)&h1,    g_h1);
    cudaGetSymbolAddress((void**)&h2,    g_h2);
    cudaGetSymbolAddress((void**)&a8,    g_a8);
    cudaGetSymbolAddress((void**)&xt8,   g_xt8);
    cudaGetSymbolAddress((void**)&a2,    g_a2);
    cudaGetSymbolAddress((void**)&h1f16, g_h1f16);
    cudaGetSymbolAddress((void**)&c1,    g_c1);
    cudaGetSymbolAddress((void**)&c2,    g_c2);
    cudaGetSymbolAddress((void**)&w1h,   g_w1h);
    cudaGetSymbolAddress((void**)&w2h,   g_w2h);

    cudaFuncSetAttribute((const void*)gemm1_fp8,
                         cudaFuncAttributeMaxDynamicSharedMemorySize, P_SMEM);
    cudaFuncSetAttribute((const void*)gemm_1t_f16,
                         cudaFuncAttributeMaxDynamicSharedMemorySize, T_SMEM);
    cudaFuncSetAttribute((const void*)gemm2_f16,
                         cudaFuncAttributeMaxDynamicSharedMemorySize, Q_SMEM);

    // one-time side stream + events (identical work every call; fork/join is
    // graph-capture legal via event edges)
    static cudaStream_t s2 = nullptr;
    static cudaEvent_t eFork = nullptr, eJoin = nullptr;
    static bool stream_ok = false;
    if (!s2) {
        stream_ok =
            (cudaStreamCreateWithFlags(&s2, cudaStreamNonBlocking) == cudaSuccess) &&
            (cudaEventCreateWithFlags(&eFork, cudaEventDisableTiming) == cudaSuccess) &&
            (cudaEventCreateWithFlags(&eJoin, cudaEventDisableTiming) == cudaSuccess);
    }
    cudaStream_t sp = stream_ok ? s2 : (cudaStream_t)0;

    // ---- fork: side stream handles all prep except scale_a8 ----
    if (stream_ok) {
        cudaEventRecord(eFork, 0);
        cudaStreamWaitEvent(sp, eFork, 0);
    }

    // main stream: the big DRAM-bound A conversion
    {
        int n8 = (B1_CNT * S1_CNT) / 8;
        scale_a8_kernel<<<n8 / 256, 256>>>(dif_mat1, a8, n8);
    }

    // side stream: everything else gemm1/tail needs
    prep_xt8_kernel<<<dim3(S1_CNT / 128, F_DIM / 64), 128, 0, sp>>>(
        features, src_idx1, src_nodes, xt8);
    gather_c1_kernel<<<B1_CNT, 128, 0, sp>>>(features, dst_idx1, src_nodes, c1);
    f32_to_f16_kernel<<<(1024 * D_DIM / 4) / 256, 256, 0, sp>>>(w1, w1h, 1024 * D_DIM / 4);
    f32_to_f16_kernel<<<(1024 * D_DIM / 4) / 256, 256, 0, sp>>>(w2, w2h, 1024 * D_DIM / 4);
    {
        int a8n = (B2_CNT * S2_CNT) / 8;
        scale_f16_kernel<<<(a8n + 255) / 256, 256, 0, sp>>>(dif_mat2, a2, a8n);
    }

    // ---- join ----
    if (stream_ok) {
        cudaEventRecord(eJoin, sp);
        cudaStreamWaitEvent((cudaStream_t)0, eJoin, 0);
    }

    // agg1 -> c1[:, 0:512] fp16 (fp8 HMMA)
    gemm1_fp8<<<dim3(F_DIM / 128, B1_CNT / 128), 512, P_SMEM>>>(a8, xt8, c1);

    // h1 = relu(c1 @ w1), co-emit fp16
    gemm_1t_f16<<<dim3(D_DIM / 128, B1_CNT / 128), 256, T_SMEM>>>(c1, w1h, h1, h1f16);

    // layer 2
    gather_c2_kernel<<<B2_CNT, 128>>>(h1f16, dst_idx2, c2);
    gemm2_f16<<<dim3(D_DIM / 128, B2_CNT / 128), 256, Q_SMEM>>>(a2, h1f16, src_idx2, c2);
    gemm_1t_f16<<<dim3(D_DIM / 128, B2_CNT / 128), 256, T_SMEM>>>(c2, w2h, h2, (__half*)nullptr);

    cls_softmax_kernel<<<B2_CNT, C_DIM>>>(h2, w_cls, out);
}